// round 2
// baseline (speedup 1.0000x reference)
#include <cuda_runtime.h>
#include <math.h>

// Problem constants (fixed by the reference: B=4096, D=1024, N_CLASSES=64)
#define NB 4096
#define ND 1024

#define MARGIN    0.09f
#define SCALE_POS 2.0f
#define SCALE_NEG 40.0f
#define EPS_C     1e-5f
#define THRESH1   0.501f
#define THRESH2   0.531f

// Scratch (module-level __device__ arrays: allowed; no runtime allocation)
__device__ float g_sim[(size_t)NB * NB];   // 64 MB similarity matrix
__device__ int   g_labels[NB];             // labels normalized to int32
__device__ float g_row[NB];                // per-row loss contribution

// ---------------------------------------------------------------------------
// Kernel 0: normalize labels to int32, auto-detecting int32 vs int64 input.
// If input is int64 (little-endian), every odd 32-bit word (high half) is 0
// since labels are in [0,64). OR of 2048 odd words == 0  =>  int64.
// Reading 4096 int32 words is in-bounds for both layouts (>=16KB buffer).
// ---------------------------------------------------------------------------
__global__ void __launch_bounds__(256) labels_kernel(const int* __restrict__ lab) {
    __shared__ int sred[256];
    __shared__ int s_is64;
    int tid = threadIdx.x;
    int acc = 0;
    for (int i = tid; i < 2048; i += 256) acc |= lab[2 * i + 1];
    sred[tid] = acc;
    __syncthreads();
    for (int o = 128; o > 0; o >>= 1) {
        if (tid < o) sred[tid] |= sred[tid + o];
        __syncthreads();
    }
    if (tid == 0) s_is64 = (sred[0] == 0) ? 1 : 0;
    __syncthreads();
    int is64 = s_is64;
    for (int i = tid; i < NB; i += 256)
        g_labels[i] = is64 ? lab[2 * i] : lab[i];
}

// ---------------------------------------------------------------------------
// Kernel 1: symmetric SGEMM  sim = F * F^T.
// Grid (32,32); CTAs with bx < by exit (upper triangle only). Each CTA
// computes a 128x128 tile and stores both the tile and its mirror (mirror
// staged through SMEM for coalesced transposed stores).
// 256 threads, 8x8 accumulator per thread, BK=8, single-stage reg prefetch.
// ---------------------------------------------------------------------------
__global__ void __launch_bounds__(256, 2) gemm_sym_kernel(const float* __restrict__ F) {
    int bx = blockIdx.x, by = blockIdx.y;
    if (bx < by) return;
    const int rowBase = by * 128;
    const int colBase = bx * 128;

    __shared__ float As[8][128];
    __shared__ float Bs[8][128];
    __shared__ float Ct[32][129];   // transpose staging (129 => conflict-free reads)

    const int tid = threadIdx.x;
    const int tx = tid & 15;        // 0..15 (column group)
    const int ty = tid >> 4;        // 0..15 (row group)

    const int lrow = tid >> 1;          // 0..127
    const int lseg = (tid & 1) * 4;     // 0 or 4

    const float* Aptr = F + (size_t)(rowBase + lrow) * ND + lseg;
    const float* Bptr = F + (size_t)(colBase + lrow) * ND + lseg;

    float acc[8][8];
#pragma unroll
    for (int i = 0; i < 8; i++)
#pragma unroll
        for (int j = 0; j < 8; j++) acc[i][j] = 0.0f;

    float4 ra = *(const float4*)(Aptr);
    float4 rb = *(const float4*)(Bptr);

    for (int k0 = 0; k0 < ND; k0 += 8) {
        As[lseg + 0][lrow] = ra.x;
        As[lseg + 1][lrow] = ra.y;
        As[lseg + 2][lrow] = ra.z;
        As[lseg + 3][lrow] = ra.w;
        Bs[lseg + 0][lrow] = rb.x;
        Bs[lseg + 1][lrow] = rb.y;
        Bs[lseg + 2][lrow] = rb.z;
        Bs[lseg + 3][lrow] = rb.w;
        __syncthreads();

        if (k0 + 8 < ND) {
            ra = *(const float4*)(Aptr + k0 + 8);
            rb = *(const float4*)(Bptr + k0 + 8);
        }

#pragma unroll
        for (int kk = 0; kk < 8; kk++) {
            float a[8], b[8];
            *(float4*)(a)     = *(const float4*)&As[kk][ty * 8];
            *(float4*)(a + 4) = *(const float4*)&As[kk][ty * 8 + 4];
            *(float4*)(b)     = *(const float4*)&Bs[kk][tx * 8];
            *(float4*)(b + 4) = *(const float4*)&Bs[kk][tx * 8 + 4];
#pragma unroll
            for (int i = 0; i < 8; i++)
#pragma unroll
                for (int j = 0; j < 8; j++)
                    acc[i][j] = fmaf(a[i], b[j], acc[i][j]);
        }
        __syncthreads();
    }

    // ---- normal (row-major) tile store, float4-coalesced from registers ----
#pragma unroll
    for (int i = 0; i < 8; i++) {
        int r = rowBase + ty * 8 + i;
        float* dst = g_sim + (size_t)r * NB + colBase + tx * 8;
        float4 v0 = make_float4(acc[i][0], acc[i][1], acc[i][2], acc[i][3]);
        float4 v1 = make_float4(acc[i][4], acc[i][5], acc[i][6], acc[i][7]);
        *(float4*)(dst)     = v0;
        *(float4*)(dst + 4) = v1;
    }

    // ---- mirror (transposed) store via SMEM staging, 32 rows per pass ----
    if (bx != by) {
        for (int p = 0; p < 4; p++) {
            __syncthreads();
            if ((ty >> 2) == p) {
                int rloc = (ty & 3) * 8;
#pragma unroll
                for (int i = 0; i < 8; i++)
#pragma unroll
                    for (int j = 0; j < 8; j++)
                        Ct[rloc + i][tx * 8 + j] = acc[i][j];
            }
            __syncthreads();
#pragma unroll
            for (int v = 0; v < 16; v++) {
                int idx = v * 256 + tid;
                int c = idx >> 5;
                int r = idx & 31;
                g_sim[(size_t)(colBase + c) * NB + rowBase + p * 32 + r] = Ct[r][c];
            }
        }
    }
}

// ---------------------------------------------------------------------------
// Kernel 2: per-row reductions. One CTA per row; row sims + labels cached in
// SMEM. Pass 1: max_neg / neg_sum / n_neg. Pass 2 (needs max_neg): pos stats.
// ---------------------------------------------------------------------------
__global__ void __launch_bounds__(256) row_kernel() {
    __shared__ float ssim[NB];
    __shared__ int   slab[NB];
    __shared__ float rf[256];
    __shared__ int   ri[256];
    __shared__ float s_maxneg, s_negsum;
    __shared__ int   s_nneg;

    const int row = blockIdx.x;
    const int tid = threadIdx.x;
    const float* srow = g_sim + (size_t)row * NB;

    for (int j = tid; j < NB; j += 256) {
        ssim[j] = srow[j];
        slab[j] = g_labels[j];
    }
    __syncthreads();

    const int rl = slab[row];

    // pass 1: negatives
    float mx = -INFINITY, ns = 0.0f;
    int nn = 0;
    for (int j = tid; j < NB; j += 256) {
        float s = ssim[j];
        if (slab[j] != rl) {
            nn++;
            ns += expf(SCALE_NEG * s);
            mx = fmaxf(mx, s);
        }
    }
    rf[tid] = mx;
    __syncthreads();
    for (int o = 128; o > 0; o >>= 1) {
        if (tid < o) rf[tid] = fmaxf(rf[tid], rf[tid + o]);
        __syncthreads();
    }
    if (tid == 0) s_maxneg = rf[0];
    __syncthreads();

    rf[tid] = ns;
    ri[tid] = nn;
    __syncthreads();
    for (int o = 128; o > 0; o >>= 1) {
        if (tid < o) { rf[tid] += rf[tid + o]; ri[tid] += ri[tid + o]; }
        __syncthreads();
    }
    if (tid == 0) { s_negsum = rf[0]; s_nneg = ri[0]; }
    __syncthreads();

    const float maxneg = s_maxneg;

    // pass 2: positives (mask depends on maxneg)
    float ps = 0.0f;
    int np = 0;
    for (int j = tid; j < NB; j += 256) {
        float s = ssim[j];
        if (slab[j] == rl && s < (1.0f - EPS_C) && (s - MARGIN) < maxneg) {
            np++;
            ps += expf(-SCALE_POS * s);
        }
    }
    __syncthreads();
    rf[tid] = ps;
    ri[tid] = np;
    __syncthreads();
    for (int o = 128; o > 0; o >>= 1) {
        if (tid < o) { rf[tid] += rf[tid + o]; ri[tid] += ri[tid + o]; }
        __syncthreads();
    }

    if (tid == 0) {
        float pos_sum = rf[0];
        int n_pos = ri[0];
        float neg_sum = s_negsum;
        int n_neg = s_nneg;
        float pos_loss = (1.0f / SCALE_POS) *
            logf((pos_sum + expf(-SCALE_POS * THRESH1)) / (float)(n_pos + 1));
        float neg_loss = (1.0f / SCALE_NEG) *
            logf((neg_sum + expf(SCALE_NEG * THRESH2)) / (float)(n_neg + 1));
        float per_row = logf(5.33f + expf(pos_loss + neg_loss));
        g_row[row] = (n_neg >= 1 && n_pos >= 1) ? per_row : 0.0f;
    }
}

// ---------------------------------------------------------------------------
// Kernel 3: deterministic final reduction of 4096 per-row values.
// ---------------------------------------------------------------------------
__global__ void __launch_bounds__(1024) final_reduce_kernel(float* __restrict__ out) {
    __shared__ float red[1024];
    int tid = threadIdx.x;
    float s = g_row[tid] + g_row[tid + 1024] + g_row[tid + 2048] + g_row[tid + 3072];
    red[tid] = s;
    __syncthreads();
    for (int o = 512; o > 0; o >>= 1) {
        if (tid < o) red[tid] += red[tid + o];
        __syncthreads();
    }
    if (tid == 0) out[0] = red[0] * (1.0f / (float)NB);
}

// ---------------------------------------------------------------------------
extern "C" void kernel_launch(void* const* d_in, const int* in_sizes, int n_in,
                              void* d_out, int out_size) {
    const float* feats = (const float*)d_in[0];
    const int* labels = (const int*)d_in[1];   // int32 view; dtype auto-detected
    float* out = (float*)d_out;

    labels_kernel<<<1, 256>>>(labels);

    dim3 grid(NB / 128, NB / 128);
    gemm_sym_kernel<<<grid, 256>>>(feats);

    row_kernel<<<NB, 256>>>();

    final_reduce_kernel<<<1, 1024>>>(out);
}

// round 4
// speedup vs baseline: 2.4606x; 2.4606x over previous
#include <cuda_runtime.h>
#include <cuda_bf16.h>
#include <math.h>
#include <stdint.h>

// Problem constants (fixed by the reference: B=4096, D=1024, N_CLASSES=64)
#define NB 4096
#define ND 1024

#define MARGIN    0.09f
#define SCALE_POS 2.0f
#define SCALE_NEG 40.0f
#define EPS_C     1e-5f
#define THRESH1   0.501f
#define THRESH2   0.531f

// -------------------- device scratch (no runtime allocation) --------------------
__device__ float         g_sim[(size_t)NB * NB];   // 64 MB similarity matrix
__device__ __nv_bfloat16 g_hi[(size_t)NB * ND];    // 8 MB bf16 high part
__device__ __nv_bfloat16 g_lo[(size_t)NB * ND];    // 8 MB bf16 residual
__device__ int           g_labels[NB];
__device__ float         g_row[NB];

// -------------------- PTX helpers (plain sm_80+ features only) --------------------
__device__ __forceinline__ uint32_t smem_u32(const void* p) {
    uint32_t a;
    asm("{ .reg .u64 t; cvta.to.shared.u64 t, %1; cvt.u32.u64 %0, t; }" : "=r"(a) : "l"(p));
    return a;
}
__device__ __forceinline__ void cp16(uint32_t s, const void* g) {
    asm volatile("cp.async.cg.shared.global [%0], [%1], 16;" :: "r"(s), "l"(g));
}
#define CP_COMMIT() asm volatile("cp.async.commit_group;" ::: "memory")
#define CP_WAIT2()  asm volatile("cp.async.wait_group 2;" ::: "memory")

__device__ __forceinline__ void ldsm4(uint32_t* r, uint32_t addr) {
    asm volatile("ldmatrix.sync.aligned.m8n8.x4.shared.b16 {%0,%1,%2,%3}, [%4];"
                 : "=r"(r[0]), "=r"(r[1]), "=r"(r[2]), "=r"(r[3]) : "r"(addr));
}
__device__ __forceinline__ void mma_bf16(float* d, const uint32_t* a,
                                         uint32_t b0, uint32_t b1) {
    asm volatile(
        "mma.sync.aligned.m16n8k16.row.col.f32.bf16.bf16.f32 "
        "{%0,%1,%2,%3}, {%4,%5,%6,%7}, {%8,%9}, {%0,%1,%2,%3};"
        : "+f"(d[0]), "+f"(d[1]), "+f"(d[2]), "+f"(d[3])
        : "r"(a[0]), "r"(a[1]), "r"(a[2]), "r"(a[3]), "r"(b0), "r"(b1));
}

// -------------------- kernel 0: labels (int64/int32 auto-detect) --------------------
__global__ void __launch_bounds__(256) labels_kernel(const int* __restrict__ lab) {
    __shared__ int sred[256];
    __shared__ int s_is64;
    int tid = threadIdx.x;
    int acc = 0;
    for (int i = tid; i < 2048; i += 256) acc |= lab[2 * i + 1];
    sred[tid] = acc;
    __syncthreads();
    for (int o = 128; o > 0; o >>= 1) {
        if (tid < o) sred[tid] |= sred[tid + o];
        __syncthreads();
    }
    if (tid == 0) s_is64 = (sred[0] == 0) ? 1 : 0;
    __syncthreads();
    int is64 = s_is64;
    for (int i = tid; i < NB; i += 256)
        g_labels[i] = is64 ? lab[2 * i] : lab[i];
}

// -------------------- kernel 1: f32 -> (hi, lo) bf16 split --------------------
__global__ void __launch_bounds__(512) convert_kernel(const float* __restrict__ F) {
    size_t i = (size_t)blockIdx.x * 512 + threadIdx.x;   // 1M threads * 4 elems
    float4 v = reinterpret_cast<const float4*>(F)[i];
    float x[4] = {v.x, v.y, v.z, v.w};
    union { __nv_bfloat16 b[4]; uint2 u; } ph, pl;
#pragma unroll
    for (int j = 0; j < 4; j++) {
        __nv_bfloat16 h = __float2bfloat16(x[j]);
        ph.b[j] = h;
        pl.b[j] = __float2bfloat16(x[j] - __bfloat162float(h));
    }
    reinterpret_cast<uint2*>(g_hi)[i] = ph.u;
    reinterpret_cast<uint2*>(g_lo)[i] = pl.u;
}

// -------------------- kernel 2: mma.sync bf16 symmetric GEMM --------------------
// sim = hi*hi^T + hi*lo^T + lo*hi^T ; 128x128 tiles, upper triangle + mirror.
// 3-stage cp.async pipeline; BK=64 (128 bytes/row, SW128 xor swizzle).
#define STAGE_BYTES 32768          // A 16KB + B 16KB
#define NCHUNK 48                  // 3 phases x 16 K-chunks of 64
#define DYNSMEM (3 * STAGE_BYTES)  // 96 KB (epilogue reuses 64 KB of it)

__device__ __forceinline__ void load_chunk(int c, uint32_t stage,
                                           int rowA, int rowB, int tid) {
    int p = c >> 4;
    int k0 = (c & 15) << 6;
    const __nv_bfloat16* Asrc = (p == 2) ? g_lo : g_hi;
    const __nv_bfloat16* Bsrc = (p == 1) ? g_lo : g_hi;
    uint32_t sB = stage + 16384;
#pragma unroll
    for (int j = 0; j < 4; j++) {
        int u = (j << 8) + tid;          // 0..1023 16B units
        int r = u >> 3;                  // row 0..127
        int ch = u & 7;                  // 16B chunk within 128B row
        uint32_t off = (uint32_t)((r << 7) + (ch << 4));
        uint32_t sw = off ^ ((off >> 3) & 0x70);
        cp16(stage + sw, Asrc + (size_t)(rowA + r) * ND + k0 + (ch << 3));
        cp16(sB + sw,    Bsrc + (size_t)(rowB + r) * ND + k0 + (ch << 3));
    }
}

__global__ void __launch_bounds__(256, 2) gemm_mma_kernel() {
    extern __shared__ char dsm[];
    if ((int)blockIdx.x < (int)blockIdx.y) return;   // upper triangle only
    const int tid = threadIdx.x;
    const int lid = tid & 31;
    const int wid = tid >> 5;
    const int tileRow = blockIdx.y * 128;
    const int tileCol = blockIdx.x * 128;

    uint32_t SB = (smem_u32(dsm) + 127u) & ~127u;

    // warp tile: 32 (M) x 64 (N); warp grid 4 x 2
    const int mRow0 = (wid >> 1) * 32;
    const int nCol0 = (wid & 1) * 64;

    // lane-invariant ldmatrix address components
    const int aRow  = lid & 15;
    const int aKsel = ((lid >> 4) & 1) * 16;
    const int bRow  = (lid & 7) + ((lid >> 4) << 3);
    const int bKsel = ((lid >> 3) & 1) * 16;

    float acc[2][8][4];
#pragma unroll
    for (int mt = 0; mt < 2; mt++)
#pragma unroll
        for (int nt = 0; nt < 8; nt++)
#pragma unroll
            for (int q = 0; q < 4; q++) acc[mt][nt][q] = 0.0f;

    load_chunk(0, SB + 0 * STAGE_BYTES, tileRow, tileCol, tid); CP_COMMIT();
    load_chunk(1, SB + 1 * STAGE_BYTES, tileRow, tileCol, tid); CP_COMMIT();

    for (int c = 0; c < NCHUNK; c++) {
        if (c + 2 < NCHUNK)
            load_chunk(c + 2, SB + ((c + 2) % 3) * STAGE_BYTES, tileRow, tileCol, tid);
        CP_COMMIT();          // (possibly empty) group keeps outstanding count uniform
        CP_WAIT2();           // this thread's chunk-c copies complete
        __syncthreads();      // all threads' copies complete

        uint32_t sa = SB + (c % 3) * STAGE_BYTES;
        uint32_t sbm = sa + 16384;
#pragma unroll
        for (int kk = 0; kk < 4; kk++) {
            uint32_t afrag[2][4];
#pragma unroll
            for (int mt = 0; mt < 2; mt++) {
                uint32_t off = (uint32_t)((mRow0 + mt * 16 + aRow) * 128 +
                                          aKsel + kk * 32);
                ldsm4(afrag[mt], sa + (off ^ ((off >> 3) & 0x70)));
            }
            uint32_t bfrag[4][4];
#pragma unroll
            for (int nt2 = 0; nt2 < 4; nt2++) {
                uint32_t off = (uint32_t)((nCol0 + nt2 * 16 + bRow) * 128 +
                                          bKsel + kk * 32);
                ldsm4(bfrag[nt2], sbm + (off ^ ((off >> 3) & 0x70)));
            }
#pragma unroll
            for (int mt = 0; mt < 2; mt++)
#pragma unroll
                for (int nt2 = 0; nt2 < 4; nt2++) {
                    mma_bf16(acc[mt][nt2 * 2],     afrag[mt], bfrag[nt2][0], bfrag[nt2][1]);
                    mma_bf16(acc[mt][nt2 * 2 + 1], afrag[mt], bfrag[nt2][2], bfrag[nt2][3]);
                }
        }
        __syncthreads();      // compute done before stage gets overwritten
    }

    // ---- epilogue: fragments -> XOR-swizzled SMEM -> normal + mirror stores ----
    // phys index for C[r][c] = r*128 + (c ^ (r & 31)); all scalar accesses are
    // bank-conflict-free for row reads, column reads, and fragment writes.
    float* C = reinterpret_cast<float*>(dsm);
#pragma unroll
    for (int mt = 0; mt < 2; mt++) {
        int r0 = mRow0 + mt * 16 + (lid >> 2);
#pragma unroll
        for (int nt = 0; nt < 8; nt++) {
            int cc = nCol0 + nt * 8 + (lid & 3) * 2;
            C[r0 * 128 + (cc ^ (r0 & 31))]             = acc[mt][nt][0];
            C[r0 * 128 + ((cc + 1) ^ (r0 & 31))]       = acc[mt][nt][1];
            int r1 = r0 + 8;
            C[r1 * 128 + (cc ^ (r1 & 31))]             = acc[mt][nt][2];
            C[r1 * 128 + ((cc + 1) ^ (r1 & 31))]       = acc[mt][nt][3];
        }
    }
    __syncthreads();

#pragma unroll 4
    for (int it = 0; it < 64; it++) {
        int idx = it * 256 + tid;
        int r = idx >> 7, cc = idx & 127;
        g_sim[(size_t)(tileRow + r) * NB + tileCol + cc] = C[r * 128 + (cc ^ (r & 31))];
    }
    if (blockIdx.x != blockIdx.y) {
#pragma unroll 4
        for (int it = 0; it < 64; it++) {
            int idx = it * 256 + tid;
            int j = idx >> 7, i = idx & 127;
            g_sim[(size_t)(tileCol + j) * NB + tileRow + i] = C[i * 128 + (j ^ (i & 31))];
        }
    }
}

// -------------------- kernel 3: per-row reductions --------------------
__global__ void __launch_bounds__(256) row_kernel() {
    __shared__ float ssim[NB];
    __shared__ int   slab[NB];
    __shared__ float rf[256];
    __shared__ int   ri[256];
    __shared__ float s_maxneg, s_negsum;
    __shared__ int   s_nneg;

    const int row = blockIdx.x;
    const int tid = threadIdx.x;
    const float* srow = g_sim + (size_t)row * NB;

    for (int j = tid; j < NB; j += 256) {
        ssim[j] = srow[j];
        slab[j] = g_labels[j];
    }
    __syncthreads();

    const int rl = slab[row];

    float mx = -INFINITY, ns = 0.0f;
    int nn = 0;
    for (int j = tid; j < NB; j += 256) {
        float s = ssim[j];
        if (slab[j] != rl) {
            nn++;
            ns += expf(SCALE_NEG * s);
            mx = fmaxf(mx, s);
        }
    }
    rf[tid] = mx;
    __syncthreads();
    for (int o = 128; o > 0; o >>= 1) {
        if (tid < o) rf[tid] = fmaxf(rf[tid], rf[tid + o]);
        __syncthreads();
    }
    if (tid == 0) s_maxneg = rf[0];
    __syncthreads();

    rf[tid] = ns;
    ri[tid] = nn;
    __syncthreads();
    for (int o = 128; o > 0; o >>= 1) {
        if (tid < o) { rf[tid] += rf[tid + o]; ri[tid] += ri[tid + o]; }
        __syncthreads();
    }
    if (tid == 0) { s_negsum = rf[0]; s_nneg = ri[0]; }
    __syncthreads();

    const float maxneg = s_maxneg;

    float ps = 0.0f;
    int np = 0;
    for (int j = tid; j < NB; j += 256) {
        float s = ssim[j];
        if (slab[j] == rl && s < (1.0f - EPS_C) && (s - MARGIN) < maxneg) {
            np++;
            ps += expf(-SCALE_POS * s);
        }
    }
    __syncthreads();
    rf[tid] = ps;
    ri[tid] = np;
    __syncthreads();
    for (int o = 128; o > 0; o >>= 1) {
        if (tid < o) { rf[tid] += rf[tid + o]; ri[tid] += ri[tid + o]; }
        __syncthreads();
    }

    if (tid == 0) {
        float pos_sum = rf[0];
        int n_pos = ri[0];
        float neg_sum = s_negsum;
        int n_neg = s_nneg;
        float pos_loss = (1.0f / SCALE_POS) *
            logf((pos_sum + expf(-SCALE_POS * THRESH1)) / (float)(n_pos + 1));
        float neg_loss = (1.0f / SCALE_NEG) *
            logf((neg_sum + expf(SCALE_NEG * THRESH2)) / (float)(n_neg + 1));
        float per_row = logf(5.33f + expf(pos_loss + neg_loss));
        g_row[row] = (n_neg >= 1 && n_pos >= 1) ? per_row : 0.0f;
    }
}

// -------------------- kernel 4: final reduce --------------------
__global__ void __launch_bounds__(1024) final_reduce_kernel(float* __restrict__ out) {
    __shared__ float red[1024];
    int tid = threadIdx.x;
    float s = g_row[tid] + g_row[tid + 1024] + g_row[tid + 2048] + g_row[tid + 3072];
    red[tid] = s;
    __syncthreads();
    for (int o = 512; o > 0; o >>= 1) {
        if (tid < o) red[tid] += red[tid + o];
        __syncthreads();
    }
    if (tid == 0) out[0] = red[0] * (1.0f / (float)NB);
}

// ---------------------------------------------------------------------------
extern "C" void kernel_launch(void* const* d_in, const int* in_sizes, int n_in,
                              void* d_out, int out_size) {
    const float* feats = (const float*)d_in[0];
    const int* labels = (const int*)d_in[1];
    float* out = (float*)d_out;

    cudaFuncSetAttribute(gemm_mma_kernel,
                         cudaFuncAttributeMaxDynamicSharedMemorySize, DYNSMEM);

    labels_kernel<<<1, 256>>>(labels);
    convert_kernel<<<2048, 512>>>(feats);            // 4M elems, 4/thread
    gemm_mma_kernel<<<dim3(32, 32), 256, DYNSMEM>>>();
    row_kernel<<<NB, 256>>>();
    final_reduce_kernel<<<1, 1024>>>(out);
}

// round 5
// speedup vs baseline: 2.9286x; 1.1902x over previous
#include <cuda_runtime.h>
#include <cuda_bf16.h>
#include <math.h>
#include <stdint.h>

// Problem constants (fixed by the reference: B=4096, D=1024, N_CLASSES=64)
#define NB 4096
#define ND 1024

#define MARGIN    0.09f
#define SCALE_POS 2.0f
#define SCALE_NEG 40.0f
#define EPS_C     1e-5f
#define THRESH1   0.501f
#define THRESH2   0.531f

// -------------------- device scratch (no runtime allocation) --------------------
__device__ float         g_sim[(size_t)NB * NB];   // 64 MB similarity matrix
__device__ __nv_bfloat16 g_hi[(size_t)NB * ND];    // 8 MB bf16 high part
__device__ __nv_bfloat16 g_lo[(size_t)NB * ND];    // 8 MB bf16 residual
__device__ int           g_labels[NB];
__device__ float         g_row[NB];

// -------------------- PTX helpers (plain sm_80+ features only) --------------------
__device__ __forceinline__ uint32_t smem_u32(const void* p) {
    uint32_t a;
    asm("{ .reg .u64 t; cvta.to.shared.u64 t, %1; cvt.u32.u64 %0, t; }" : "=r"(a) : "l"(p));
    return a;
}
__device__ __forceinline__ void cp16(uint32_t s, const void* g) {
    asm volatile("cp.async.cg.shared.global [%0], [%1], 16;" :: "r"(s), "l"(g));
}
#define CP_COMMIT() asm volatile("cp.async.commit_group;" ::: "memory")
#define CP_WAIT2()  asm volatile("cp.async.wait_group 2;" ::: "memory")

__device__ __forceinline__ void ldsm4(uint32_t* r, uint32_t addr) {
    asm volatile("ldmatrix.sync.aligned.m8n8.x4.shared.b16 {%0,%1,%2,%3}, [%4];"
                 : "=r"(r[0]), "=r"(r[1]), "=r"(r[2]), "=r"(r[3]) : "r"(addr));
}
__device__ __forceinline__ void mma_bf16(float* d, const uint32_t* a,
                                         uint32_t b0, uint32_t b1) {
    asm volatile(
        "mma.sync.aligned.m16n8k16.row.col.f32.bf16.bf16.f32 "
        "{%0,%1,%2,%3}, {%4,%5,%6,%7}, {%8,%9}, {%0,%1,%2,%3};"
        : "+f"(d[0]), "+f"(d[1]), "+f"(d[2]), "+f"(d[3])
        : "r"(a[0]), "r"(a[1]), "r"(a[2]), "r"(a[3]), "r"(b0), "r"(b1));
}

// -------------------- kernel 0: labels (int64/int32 auto-detect) --------------------
__global__ void __launch_bounds__(256) labels_kernel(const int* __restrict__ lab) {
    __shared__ int sred[256];
    __shared__ int s_is64;
    int tid = threadIdx.x;
    int acc = 0;
    for (int i = tid; i < 2048; i += 256) acc |= lab[2 * i + 1];
    sred[tid] = acc;
    __syncthreads();
    for (int o = 128; o > 0; o >>= 1) {
        if (tid < o) sred[tid] |= sred[tid + o];
        __syncthreads();
    }
    if (tid == 0) s_is64 = (sred[0] == 0) ? 1 : 0;
    __syncthreads();
    int is64 = s_is64;
    for (int i = tid; i < NB; i += 256)
        g_labels[i] = is64 ? lab[2 * i] : lab[i];
}

// -------------------- kernel 1: f32 -> (hi, lo) bf16 split --------------------
__global__ void __launch_bounds__(512) convert_kernel(const float* __restrict__ F) {
    size_t i = (size_t)blockIdx.x * 512 + threadIdx.x;   // 1M threads * 4 elems
    float4 v = reinterpret_cast<const float4*>(F)[i];
    float x[4] = {v.x, v.y, v.z, v.w};
    union { __nv_bfloat16 b[4]; uint2 u; } ph, pl;
#pragma unroll
    for (int j = 0; j < 4; j++) {
        __nv_bfloat16 h = __float2bfloat16(x[j]);
        ph.b[j] = h;
        pl.b[j] = __float2bfloat16(x[j] - __bfloat162float(h));
    }
    reinterpret_cast<uint2*>(g_hi)[i] = ph.u;
    reinterpret_cast<uint2*>(g_lo)[i] = pl.u;
}

// -------------------- kernel 2: mma.sync bf16 symmetric GEMM --------------------
// sim = hi*hi^T + hi*lo^T + lo*hi^T ; 128x128 tiles, upper triangle + mirror.
#define STAGE_BYTES 32768          // A 16KB + B 16KB
#define NCHUNK 48                  // 3 phases x 16 K-chunks of 64
#define DYNSMEM (3 * STAGE_BYTES)  // 96 KB (epilogue reuses 64 KB of it)

__device__ __forceinline__ void load_chunk(int c, uint32_t stage,
                                           int rowA, int rowB, int tid) {
    int p = c >> 4;
    int k0 = (c & 15) << 6;
    const __nv_bfloat16* Asrc = (p == 2) ? g_lo : g_hi;
    const __nv_bfloat16* Bsrc = (p == 1) ? g_lo : g_hi;
    uint32_t sB = stage + 16384;
#pragma unroll
    for (int j = 0; j < 4; j++) {
        int u = (j << 8) + tid;          // 0..1023 16B units
        int r = u >> 3;                  // row 0..127
        int ch = u & 7;                  // 16B chunk within 128B row
        uint32_t off = (uint32_t)((r << 7) + (ch << 4));
        uint32_t sw = off ^ ((off >> 3) & 0x70);
        cp16(stage + sw, Asrc + (size_t)(rowA + r) * ND + k0 + (ch << 3));
        cp16(sB + sw,    Bsrc + (size_t)(rowB + r) * ND + k0 + (ch << 3));
    }
}

__global__ void __launch_bounds__(256, 2) gemm_mma_kernel() {
    extern __shared__ char dsm[];
    if ((int)blockIdx.x < (int)blockIdx.y) return;   // upper triangle only
    const int tid = threadIdx.x;
    const int lid = tid & 31;
    const int wid = tid >> 5;
    const int tileRow = blockIdx.y * 128;
    const int tileCol = blockIdx.x * 128;

    uint32_t SB = (smem_u32(dsm) + 127u) & ~127u;

    const int mRow0 = (wid >> 1) * 32;
    const int nCol0 = (wid & 1) * 64;

    const int aRow  = lid & 15;
    const int aKsel = ((lid >> 4) & 1) * 16;
    const int bRow  = (lid & 7) + ((lid >> 4) << 3);
    const int bKsel = ((lid >> 3) & 1) * 16;

    float acc[2][8][4];
#pragma unroll
    for (int mt = 0; mt < 2; mt++)
#pragma unroll
        for (int nt = 0; nt < 8; nt++)
#pragma unroll
            for (int q = 0; q < 4; q++) acc[mt][nt][q] = 0.0f;

    load_chunk(0, SB + 0 * STAGE_BYTES, tileRow, tileCol, tid); CP_COMMIT();
    load_chunk(1, SB + 1 * STAGE_BYTES, tileRow, tileCol, tid); CP_COMMIT();

    for (int c = 0; c < NCHUNK; c++) {
        if (c + 2 < NCHUNK)
            load_chunk(c + 2, SB + ((c + 2) % 3) * STAGE_BYTES, tileRow, tileCol, tid);
        CP_COMMIT();
        CP_WAIT2();
        __syncthreads();

        uint32_t sa = SB + (c % 3) * STAGE_BYTES;
        uint32_t sbm = sa + 16384;
#pragma unroll
        for (int kk = 0; kk < 4; kk++) {
            uint32_t afrag[2][4];
#pragma unroll
            for (int mt = 0; mt < 2; mt++) {
                uint32_t off = (uint32_t)((mRow0 + mt * 16 + aRow) * 128 +
                                          aKsel + kk * 32);
                ldsm4(afrag[mt], sa + (off ^ ((off >> 3) & 0x70)));
            }
            uint32_t bfrag[4][4];
#pragma unroll
            for (int nt2 = 0; nt2 < 4; nt2++) {
                uint32_t off = (uint32_t)((nCol0 + nt2 * 16 + bRow) * 128 +
                                          bKsel + kk * 32);
                ldsm4(bfrag[nt2], sbm + (off ^ ((off >> 3) & 0x70)));
            }
#pragma unroll
            for (int mt = 0; mt < 2; mt++)
#pragma unroll
                for (int nt2 = 0; nt2 < 4; nt2++) {
                    mma_bf16(acc[mt][nt2 * 2],     afrag[mt], bfrag[nt2][0], bfrag[nt2][1]);
                    mma_bf16(acc[mt][nt2 * 2 + 1], afrag[mt], bfrag[nt2][2], bfrag[nt2][3]);
                }
        }
        __syncthreads();
    }

    // ---- epilogue: fragments -> XOR-swizzled SMEM -> normal + mirror stores ----
    float* C = reinterpret_cast<float*>(dsm);
#pragma unroll
    for (int mt = 0; mt < 2; mt++) {
        int r0 = mRow0 + mt * 16 + (lid >> 2);
#pragma unroll
        for (int nt = 0; nt < 8; nt++) {
            int cc = nCol0 + nt * 8 + (lid & 3) * 2;
            C[r0 * 128 + (cc ^ (r0 & 31))]       = acc[mt][nt][0];
            C[r0 * 128 + ((cc + 1) ^ (r0 & 31))] = acc[mt][nt][1];
            int r1 = r0 + 8;
            C[r1 * 128 + (cc ^ (r1 & 31))]       = acc[mt][nt][2];
            C[r1 * 128 + ((cc + 1) ^ (r1 & 31))] = acc[mt][nt][3];
        }
    }
    __syncthreads();

#pragma unroll 4
    for (int it = 0; it < 64; it++) {
        int idx = it * 256 + tid;
        int r = idx >> 7, cc = idx & 127;
        g_sim[(size_t)(tileRow + r) * NB + tileCol + cc] = C[r * 128 + (cc ^ (r & 31))];
    }
    if (blockIdx.x != blockIdx.y) {
#pragma unroll 4
        for (int it = 0; it < 64; it++) {
            int idx = it * 256 + tid;
            int j = idx >> 7, i = idx & 127;
            g_sim[(size_t)(tileCol + j) * NB + tileRow + i] = C[i * 128 + (j ^ (i & 31))];
        }
    }
}

// -------------------- kernel 3: per-row reductions (register-resident) --------------------
// One CTA per row, 256 threads x 16 columns each. Sims held in registers, labels
// via L1-cached int4 loads, predicate bitmasks reused in pass 2, shuffle reductions.
__global__ void __launch_bounds__(256) row_kernel() {
    const int row = blockIdx.x;
    const int tid = threadIdx.x;
    const int lid = tid & 31;
    const int wrp = tid >> 5;

    __shared__ float wmx[8], wns[8], wps[8];
    __shared__ int   wnn[8], wnp[8];
    __shared__ float s_maxneg, s_negsum;
    __shared__ int   s_nneg;

    const float4* srow = reinterpret_cast<const float4*>(g_sim + (size_t)row * NB);
    const int4*   lab4 = reinterpret_cast<const int4*>(g_labels);
    const int rl = g_labels[row];

    float s[16];
    uint32_t m_neq = 0;   // bit q: label != rl
    uint32_t m_pc  = 0;   // bit q: label == rl && s < 1-eps  (pos candidate)

    float mx = -INFINITY, ns = 0.0f;
    int nn = 0;

#pragma unroll
    for (int it = 0; it < 4; it++) {
        float4 v = srow[it * 256 + tid];
        int4 L = lab4[it * 256 + tid];
        s[it * 4 + 0] = v.x; s[it * 4 + 1] = v.y;
        s[it * 4 + 2] = v.z; s[it * 4 + 3] = v.w;
        int l[4] = {L.x, L.y, L.z, L.w};
#pragma unroll
        for (int q = 0; q < 4; q++) {
            float sv = s[it * 4 + q];
            bool neq = (l[q] != rl);
            if (neq) {
                m_neq |= (1u << (it * 4 + q));
                nn++;
                ns += __expf(SCALE_NEG * sv);
                mx = fmaxf(mx, sv);
            } else if (sv < (1.0f - EPS_C)) {
                m_pc |= (1u << (it * 4 + q));
            }
        }
    }

    // warp-level reduce (max, sum, count)
#pragma unroll
    for (int o = 16; o > 0; o >>= 1) {
        mx = fmaxf(mx, __shfl_xor_sync(0xFFFFFFFFu, mx, o));
        ns += __shfl_xor_sync(0xFFFFFFFFu, ns, o);
        nn += __shfl_xor_sync(0xFFFFFFFFu, nn, o);
    }
    if (lid == 0) { wmx[wrp] = mx; wns[wrp] = ns; wnn[wrp] = nn; }
    __syncthreads();
    if (wrp == 0) {
        float m2 = (lid < 8) ? wmx[lid] : -INFINITY;
        float n2 = (lid < 8) ? wns[lid] : 0.0f;
        int   c2 = (lid < 8) ? wnn[lid] : 0;
#pragma unroll
        for (int o = 4; o > 0; o >>= 1) {
            m2 = fmaxf(m2, __shfl_xor_sync(0xFFFFFFFFu, m2, o));
            n2 += __shfl_xor_sync(0xFFFFFFFFu, n2, o);
            c2 += __shfl_xor_sync(0xFFFFFFFFu, c2, o);
        }
        if (lid == 0) { s_maxneg = m2; s_negsum = n2; s_nneg = c2; }
    }
    __syncthreads();

    const float maxneg = s_maxneg;

    // pass 2: positives from registers + bitmask
    float ps = 0.0f;
    int np = 0;
    uint32_t m = m_pc;
#pragma unroll
    for (int q = 0; q < 16; q++) {
        if (m & (1u << q)) {
            float sv = s[q];
            if ((sv - MARGIN) < maxneg) {
                np++;
                ps += __expf(-SCALE_POS * sv);
            }
        }
    }
#pragma unroll
    for (int o = 16; o > 0; o >>= 1) {
        ps += __shfl_xor_sync(0xFFFFFFFFu, ps, o);
        np += __shfl_xor_sync(0xFFFFFFFFu, np, o);
    }
    if (lid == 0) { wps[wrp] = ps; wnp[wrp] = np; }
    __syncthreads();
    if (tid == 0) {
        float pos_sum = 0.0f;
        int n_pos = 0;
#pragma unroll
        for (int w = 0; w < 8; w++) { pos_sum += wps[w]; n_pos += wnp[w]; }
        float neg_sum = s_negsum;
        int n_neg = s_nneg;
        float pos_loss = (1.0f / SCALE_POS) *
            __logf((pos_sum + __expf(-SCALE_POS * THRESH1)) / (float)(n_pos + 1));
        float neg_loss = (1.0f / SCALE_NEG) *
            __logf((neg_sum + __expf(SCALE_NEG * THRESH2)) / (float)(n_neg + 1));
        float per_row = __logf(5.33f + __expf(pos_loss + neg_loss));
        g_row[row] = (n_neg >= 1 && n_pos >= 1) ? per_row : 0.0f;
    }
}

// -------------------- kernel 4: final reduce (float4 + shuffle) --------------------
__global__ void __launch_bounds__(256) final_reduce_kernel(float* __restrict__ out) {
    __shared__ float wsum[8];
    int tid = threadIdx.x;
    int lid = tid & 31, wrp = tid >> 5;
    const float4* r4 = reinterpret_cast<const float4*>(g_row);
    float s = 0.0f;
#pragma unroll
    for (int it = 0; it < 4; it++) {
        float4 v = r4[it * 256 + tid];
        s += (v.x + v.y) + (v.z + v.w);
    }
#pragma unroll
    for (int o = 16; o > 0; o >>= 1) s += __shfl_xor_sync(0xFFFFFFFFu, s, o);
    if (lid == 0) wsum[wrp] = s;
    __syncthreads();
    if (tid == 0) {
        float t = 0.0f;
#pragma unroll
        for (int w = 0; w < 8; w++) t += wsum[w];
        out[0] = t * (1.0f / (float)NB);
    }
}

// ---------------------------------------------------------------------------
extern "C" void kernel_launch(void* const* d_in, const int* in_sizes, int n_in,
                              void* d_out, int out_size) {
    const float* feats = (const float*)d_in[0];
    const int* labels = (const int*)d_in[1];
    float* out = (float*)d_out;

    cudaFuncSetAttribute(gemm_mma_kernel,
                         cudaFuncAttributeMaxDynamicSharedMemorySize, DYNSMEM);

    labels_kernel<<<1, 256>>>(labels);
    convert_kernel<<<2048, 512>>>(feats);            // 4M elems, 4/thread
    gemm_mma_kernel<<<dim3(32, 32), 256, DYNSMEM>>>();
    row_kernel<<<NB, 256>>>();
    final_reduce_kernel<<<1, 256>>>(out);
}